// round 17
// baseline (speedup 1.0000x reference)
#include <cuda_runtime.h>
#include <cuda_bf16.h>
#include <stdint.h>
#include <math.h>

#define Bv    32
#define NCLS  20
#define Tt    2048
#define Dd    2048
#define Ll    128

// FSD scale: 10*log2(e)  (gamma=0.1 -> log2 x10 domain); back: ln(2)/10
#define FSD_SCALE 14.426950408889634f
#define FSD_UNSCALE 0.06931471805599453f

// ---------------------------------------------------------------------------
// Device scratch
// ---------------------------------------------------------------------------
__device__ float g_sim_m[32 * Ll * Ll];     // FSD m (x FSD_SCALE)
__device__ float g_sim_g[32 * Ll * Ll];     // FSD g (x FSD_SCALE)
__device__ float g_dotL0[32 * Ll * Ll];     // LCS raw dots, K half 0
__device__ float g_dotL1[32 * Ll * Ll];     // LCS raw dots, K half 1
__device__ float g_nAL[2][32][128];         // LCS A sq partials
__device__ float g_nBL[2][32][128];         // LCS B sq partials
__device__ float g_small[32][4];            // per-batch {cls, guide, feat, sparse}
__device__ float g_dpres[64];               // 0..31 fsd, 32..63 lcs
__device__ unsigned int g_done = 0;

// ---------------------------------------------------------------------------
// GEMM helpers
// ---------------------------------------------------------------------------
__device__ __forceinline__ uint32_t swz(uint32_t row, uint32_t col) {
    return row * 64u + ((((col >> 3) ^ ((row >> 1) & 3u)) << 4)) + ((col & 7u) << 1);
}
__device__ __forceinline__ uint32_t pk_bf2(float lo, float hi) {
    __nv_bfloat162 h = __floats2bfloat162_rn(lo, hi);
    return *(uint32_t*)&h;
}
__device__ __forceinline__ void ldsm4(uint32_t addr, uint32_t& r0, uint32_t& r1,
                                      uint32_t& r2, uint32_t& r3) {
    asm volatile("ldmatrix.sync.aligned.m8n8.x4.shared.b16 {%0,%1,%2,%3}, [%4];"
                 : "=r"(r0), "=r"(r1), "=r"(r2), "=r"(r3) : "r"(addr));
}
__device__ __forceinline__ void mma16816(float* c, const uint32_t* a,
                                         uint32_t b0, uint32_t b1) {
    asm volatile("mma.sync.aligned.m16n8k16.row.col.f32.bf16.bf16.f32 "
                 "{%0,%1,%2,%3}, {%4,%5,%6,%7}, {%8,%9}, {%0,%1,%2,%3};"
                 : "+f"(c[0]), "+f"(c[1]), "+f"(c[2]), "+f"(c[3])
                 : "r"(a[0]), "r"(a[1]), "r"(a[2]), "r"(a[3]), "r"(b0), "r"(b1));
}

#define STAGE_BYTES 12288
#define KSTEPS 32

// ---------------------------------------------------------------------------
// k_gemm: 288 blocks (unchanged from best).
// ---------------------------------------------------------------------------
__global__ __launch_bounds__(256, 2)
void k_gemm(const float* __restrict__ lcs,
            const float* __restrict__ act,
            const float* __restrict__ bak,
            const int* __restrict__ pos,
            const int* __restrict__ neg,
            const float* __restrict__ xi,
            const float* __restrict__ xc,
            const float* __restrict__ xb,
            const float* __restrict__ vid,
            const float* __restrict__ att,
            const float* __restrict__ fi,
            const float* __restrict__ fc,
            const float* __restrict__ fb,
            const float* __restrict__ cas) {
    int blk = blockIdx.x;
    int tid = threadIdx.x;

    __shared__ uint4 smBuf[2 * STAGE_BYTES / 16];
    __shared__ float rnAs[128];
    __shared__ float rnBs[64];

    if (blk >= 256) {
        __shared__ float red[256];
        int bb = blk - 256;
        float guide = 0.0f, sparse = 0.0f, si2 = 0.0f, sc2 = 0.0f, sb2 = 0.0f;
        for (int tt = tid; tt < Tt; tt += 256) {
            float cas20 = cas[((size_t)bb * Tt + tt) * (NCLS + 1) + NCLS];
            float a0 = att[((size_t)bb * Tt + tt) * 3 + 0];
            float a1 = att[((size_t)bb * Tt + tt) * 3 + 1];
            guide  += fabsf(1.0f - cas20 - a0);
            sparse += a0 + a1;
        }
        for (int k = tid; k < Dd; k += 256) {
            float v1 = fi[(size_t)bb * Dd + k];
            float v2 = fc[(size_t)bb * Dd + k];
            float v3 = fb[(size_t)bb * Dd + k];
            si2 += v1 * v1; sc2 += v2 * v2; sb2 += v3 * v3;
        }
        float vals[5] = {guide, sparse, si2, sc2, sb2};
#pragma unroll
        for (int v = 0; v < 5; ++v) {
            red[tid] = vals[v];
            __syncthreads();
            for (int s = 128; s > 0; s >>= 1) {
                if (tid < s) red[tid] += red[tid + s];
                __syncthreads();
            }
            vals[v] = red[0];
            __syncthreads();
        }
        if (tid == 0) {
            float ni = sqrtf(vals[2]);
            float nc = sqrtf(vals[3]);
            float nb = sqrtf(vals[4]);
            float f1 = fmaxf(50.0f - ni + nc, 0.0f);
            float f2 = fmaxf(50.0f - nc + nb, 0.0f);
            float feat = (f1 + f2 + nb) * (f1 + f2 + nb);
            float sv = 0.0f, s_i = 0.0f, s_c = 0.0f;
            for (int c = 0; c < NCLS; ++c) {
                float l = vid[bb * NCLS + c];
                sv  += l;
                s_i += l * logf(xi[bb * (NCLS + 1) + c] + 1e-45f);
                s_c += l * logf(xc[bb * (NCLS + 1) + c] + 1e-45f);
            }
            float inst_b = -s_i / sv;
            float cont_b = -(s_c + logf(xc[bb * (NCLS + 1) + NCLS] + 1e-45f)) / (sv + 1.0f);
            float back_b = -logf(xb[bb * (NCLS + 1) + NCLS] + 1e-45f);
            g_small[bb][0] = inst_b + cont_b + back_b;
            g_small[bb][1] = vals[0];
            g_small[bb][2] = feat;
            g_small[bb][3] = vals[1];
        }
        return;
    }

    const float *Abase, *Bbase;
    float* out;
    int mode, colTile, p_idx, kh = 0;

    if (blk < 128) {
        int f = blk >> 1;
        colTile = (blk & 1) * 64;
        int p = f >> 1;
        int half = f & 1;
        p_idx = p;
        int i0 = (p < 16) ? pos[2 * p]     : neg[2 * (p - 16)];
        int i1 = (p < 16) ? pos[2 * p + 1] : neg[2 * (p - 16) + 1];
        Abase = act + (size_t)i0 * Ll * Dd + half * 1024;
        if (p < 16)
            Bbase = act + (size_t)i1 * Ll * Dd + half * 1024;
        else
            Bbase = bak + (size_t)i1 * Ll * Dd + half * 1024;
        out = (half ? g_sim_g : g_sim_m) + (size_t)p * Ll * Ll;
        mode = 0;
    } else {
        int q = blk - 128;
        int p = q >> 2;
        colTile = ((q >> 1) & 1) * 64;
        kh = q & 1;
        p_idx = p;
        int i0 = (p < 16) ? pos[2 * p]     : neg[2 * (p - 16)];
        int i1 = (p < 16) ? pos[2 * p + 1] : neg[2 * (p - 16) + 1];
        Abase = lcs + (size_t)i0 * Ll * Dd + kh * 1024;
        Bbase = lcs + (size_t)i1 * Ll * Dd + kh * 1024;
        out = (kh ? g_dotL1 : g_dotL0) + (size_t)p * Ll * Ll;
        mode = 1;
    }
    Bbase += (size_t)colTile * Dd;

    char* smc = (char*)smBuf;
    uint32_t smemBase = (uint32_t)__cvta_generic_to_shared(smc);

    int lane = tid & 31;
    int warp = tid >> 5;
    int wm = warp >> 1;
    int wn = warp & 1;

    int aRow0 = tid >> 2,            aKg0 = tid & 3;
    int aRow1 = (tid + 256) >> 2,    aKg1 = tid & 3;
    int bRow  = tid >> 2,            bKg  = tid & 3;

    float acc[2][4][4];
#pragma unroll
    for (int i = 0; i < 2; ++i)
#pragma unroll
        for (int j = 0; j < 4; ++j)
#pragma unroll
            for (int q2 = 0; q2 < 4; ++q2) acc[i][j][q2] = 0.0f;

    float sqA0 = 0.0f, sqA1 = 0.0f, sqB = 0.0f;
    float4 bufA[2][2], bufB[2];

    const float* pA0 = Abase + (size_t)aRow0 * Dd + aKg0 * 8;
    const float* pA1 = Abase + (size_t)aRow1 * Dd + aKg1 * 8;
    const float* pB  = Bbase + (size_t)bRow  * Dd + bKg  * 8;

    bufA[0][0] = *(const float4*)(pA0);
    bufA[0][1] = *(const float4*)(pA0 + 4);
    bufA[1][0] = *(const float4*)(pA1);
    bufA[1][1] = *(const float4*)(pA1 + 4);
    bufB[0]    = *(const float4*)(pB);
    bufB[1]    = *(const float4*)(pB + 4);

    {
        const float* fa0 = (const float*)&bufA[0][0];
        const float* fa1 = (const float*)&bufA[1][0];
        const float* fbb = (const float*)&bufB[0];
#pragma unroll
        for (int q2 = 0; q2 < 8; ++q2) {
            sqA0 = fmaf(fa0[q2], fa0[q2], sqA0);
            sqA1 = fmaf(fa1[q2], fa1[q2], sqA1);
            sqB  = fmaf(fbb[q2], fbb[q2], sqB);
        }
        uint4 v;
        v.x = pk_bf2(fa0[0], fa0[1]); v.y = pk_bf2(fa0[2], fa0[3]);
        v.z = pk_bf2(fa0[4], fa0[5]); v.w = pk_bf2(fa0[6], fa0[7]);
        *(uint4*)(smc + swz(aRow0, aKg0 * 8)) = v;
        v.x = pk_bf2(fa1[0], fa1[1]); v.y = pk_bf2(fa1[2], fa1[3]);
        v.z = pk_bf2(fa1[4], fa1[5]); v.w = pk_bf2(fa1[6], fa1[7]);
        *(uint4*)(smc + swz(aRow1, aKg1 * 8)) = v;
        v.x = pk_bf2(fbb[0], fbb[1]); v.y = pk_bf2(fbb[2], fbb[3]);
        v.z = pk_bf2(fbb[4], fbb[5]); v.w = pk_bf2(fbb[6], fbb[7]);
        *(uint4*)(smc + 8192 + swz(bRow, bKg * 8)) = v;
    }
    __syncthreads();

    int grp = lane >> 3, r8 = lane & 7;
    uint32_t aRowL = (uint32_t)(r8 + (grp & 1) * 8);
    uint32_t aColL = (uint32_t)((grp >> 1) * 8);
    uint32_t bRowL = (uint32_t)(r8 + (grp >> 1) * 8);
    uint32_t bColL = (uint32_t)((grp & 1) * 8);

    for (int kt = 0; kt < KSTEPS; ++kt) {
        if (kt + 1 < KSTEPS) {
            int k0 = (kt + 1) * 32;
            bufA[0][0] = *(const float4*)(pA0 + k0);
            bufA[0][1] = *(const float4*)(pA0 + k0 + 4);
            bufA[1][0] = *(const float4*)(pA1 + k0);
            bufA[1][1] = *(const float4*)(pA1 + k0 + 4);
            bufB[0]    = *(const float4*)(pB + k0);
            bufB[1]    = *(const float4*)(pB + k0 + 4);
        }

        uint32_t stBase = smemBase + (uint32_t)(kt & 1) * STAGE_BYTES;
#pragma unroll
        for (int ks = 0; ks < 2; ++ks) {
            int k0 = ks * 16;
            uint32_t afr[2][4];
#pragma unroll
            for (int tm = 0; tm < 2; ++tm) {
                uint32_t m0 = (uint32_t)(wm * 32 + tm * 16);
                uint32_t addrA = stBase + swz(m0 + aRowL, (uint32_t)k0 + aColL);
                ldsm4(addrA, afr[tm][0], afr[tm][1], afr[tm][2], afr[tm][3]);
            }
            uint32_t bfr[2][4];
#pragma unroll
            for (int tb = 0; tb < 2; ++tb) {
                uint32_t n0 = (uint32_t)(wn * 32 + tb * 16);
                uint32_t addrB = stBase + 8192u + swz(n0 + bRowL, (uint32_t)k0 + bColL);
                ldsm4(addrB, bfr[tb][0], bfr[tb][1], bfr[tb][2], bfr[tb][3]);
            }
#pragma unroll
            for (int tm = 0; tm < 2; ++tm)
#pragma unroll
                for (int tn = 0; tn < 4; ++tn) {
                    int tb = tn >> 1, wh = tn & 1;
                    mma16816(acc[tm][tn], afr[tm], bfr[tb][wh * 2], bfr[tb][wh * 2 + 1]);
                }
        }

        if (kt + 1 < KSTEPS) {
            char* nst = smc + ((kt + 1) & 1) * STAGE_BYTES;
            const float* fa0 = (const float*)&bufA[0][0];
            const float* fa1 = (const float*)&bufA[1][0];
            const float* fbb = (const float*)&bufB[0];
#pragma unroll
            for (int q2 = 0; q2 < 8; ++q2) {
                sqA0 = fmaf(fa0[q2], fa0[q2], sqA0);
                sqA1 = fmaf(fa1[q2], fa1[q2], sqA1);
                sqB  = fmaf(fbb[q2], fbb[q2], sqB);
            }
            uint4 v;
            v.x = pk_bf2(fa0[0], fa0[1]); v.y = pk_bf2(fa0[2], fa0[3]);
            v.z = pk_bf2(fa0[4], fa0[5]); v.w = pk_bf2(fa0[6], fa0[7]);
            *(uint4*)(nst + swz(aRow0, aKg0 * 8)) = v;
            v.x = pk_bf2(fa1[0], fa1[1]); v.y = pk_bf2(fa1[2], fa1[3]);
            v.z = pk_bf2(fa1[4], fa1[5]); v.w = pk_bf2(fa1[6], fa1[7]);
            *(uint4*)(nst + swz(aRow1, aKg1 * 8)) = v;
            v.x = pk_bf2(fbb[0], fbb[1]); v.y = pk_bf2(fbb[2], fbb[3]);
            v.z = pk_bf2(fbb[4], fbb[5]); v.w = pk_bf2(fbb[6], fbb[7]);
            *(uint4*)(nst + 8192 + swz(bRow, bKg * 8)) = v;
        }
        __syncthreads();
    }

    sqA0 += __shfl_xor_sync(0xffffffffu, sqA0, 1);
    sqA0 += __shfl_xor_sync(0xffffffffu, sqA0, 2);
    sqA1 += __shfl_xor_sync(0xffffffffu, sqA1, 1);
    sqA1 += __shfl_xor_sync(0xffffffffu, sqA1, 2);
    sqB  += __shfl_xor_sync(0xffffffffu, sqB, 1);
    sqB  += __shfl_xor_sync(0xffffffffu, sqB, 2);

    if (mode == 1) {
        if ((tid & 3) == 0) {
            g_nAL[kh][p_idx][aRow0] = sqA0;
            g_nAL[kh][p_idx][aRow1] = sqA1;
            g_nBL[kh][p_idx][colTile + bRow] = sqB;
        }
        int g8 = lane >> 2, tq = lane & 3;
#pragma unroll
        for (int tm = 0; tm < 2; ++tm) {
            int row0 = wm * 32 + tm * 16 + g8;
            int row1 = row0 + 8;
#pragma unroll
            for (int tn = 0; tn < 4; ++tn) {
                int col = colTile + wn * 32 + tn * 8 + 2 * tq;
                *(float2*)(out + row0 * Ll + col) =
                    make_float2(acc[tm][tn][0], acc[tm][tn][1]);
                *(float2*)(out + row1 * Ll + col) =
                    make_float2(acc[tm][tn][2], acc[tm][tn][3]);
            }
        }
        return;
    }

    if ((tid & 3) == 0) {
        rnAs[aRow0] = rsqrtf(sqA0);
        rnAs[aRow1] = rsqrtf(sqA1);
        rnBs[bRow]  = rsqrtf(sqB);
    }
    __syncthreads();

    int g8 = lane >> 2, tq = lane & 3;
#pragma unroll
    for (int tm = 0; tm < 2; ++tm) {
        int row0 = wm * 32 + tm * 16 + g8;
        int row1 = row0 + 8;
        float ra0 = rnAs[row0], ra1 = rnAs[row1];
#pragma unroll
        for (int tn = 0; tn < 4; ++tn) {
            int lcol = wn * 32 + tn * 8 + 2 * tq;
            int col = colTile + lcol;
            float rb0 = rnBs[lcol], rb1 = rnBs[lcol + 1];
            float v00 = acc[tm][tn][0] * ra0 * rb0 * FSD_SCALE;
            float v01 = acc[tm][tn][1] * ra0 * rb1 * FSD_SCALE;
            float v10 = acc[tm][tn][2] * ra1 * rb0 * FSD_SCALE;
            float v11 = acc[tm][tn][3] * ra1 * rb1 * FSD_SCALE;
            *(float2*)(out + row0 * Ll + col) = make_float2(v00, v01);
            *(float2*)(out + row1 * Ll + col) = make_float2(v10, v11);
        }
    }
}

// ---------------------------------------------------------------------------
// k_dp: 64 blocks x 128 threads. 2-ROW-BLOCK wavefront: lane owns row-pair
// p = 32w + lane (rows 2p, 2p+1); at step s it computes both cells of column
// j = s - p. Steps 255 -> 191; one shfl / one bnd / one LDS.128 per 2 cells.
// 2 DP warps with lag-1 epoch schedule (DPK=8); warps 2,3 only barrier.
// FSD smem: float4[p*128+j] = {m_top, g_top, m_bot, g_bot};
// LCS smem: float2[p*128+j] = {s_top, s_bot}.
// ---------------------------------------------------------------------------
__device__ __forceinline__ float ex2f(float x) {
    float y; asm("ex2.approx.f32 %0, %1;" : "=f"(y) : "f"(x)); return y;
}
__device__ __forceinline__ float lg2f(float x) {
    float y; asm("lg2.approx.f32 %0, %1;" : "=f"(y) : "f"(x)); return y;
}

#define DPK2 8
#define NE   24     // epochs: 24*8 = 192 slots cover s in [0,191)
#define NSUP2 25    // warp w in {0,1} active tau in [w, w+NE)

__global__ void k_dp(float* __restrict__ outp) {
    extern __shared__ float dsm[];
    __shared__ float bnd[3][192];       // 0,1 per-warp boundaries; 2 = zeros
    int b = blockIdx.x;
    int tid = threadIdx.x;
    bool isFsd = (b < 32);
    int pair = isFsd ? b : b - 32;

    if (isFsd) {
        // pack per (row-pair p, col j): float4 {m_top, g_top, m_bot, g_bot}
        float2* d2 = (float2*)dsm;     // float2 idx = (p*128 + j)*2 + parity
        const float4* Mb = (const float4*)(g_sim_m + (size_t)pair * 16384);
        const float4* Gb = (const float4*)(g_sim_g + (size_t)pair * 16384);
        for (int i = tid; i < 4096; i += 128) {
            int row = i >> 5, c0 = (i & 31) * 4;
            float4 m4 = Mb[i];
            float4 g4 = Gb[i];
            int base = ((row >> 1) * 128 + c0) * 2 + (row & 1);
            d2[base + 0] = make_float2(m4.x, g4.x);
            d2[base + 2] = make_float2(m4.y, g4.y);
            d2[base + 4] = make_float2(m4.z, g4.z);
            d2[base + 6] = make_float2(m4.w, g4.w);
        }
    } else {
        // fused LCS split-K epilogue into packed float2 {s_top, s_bot}
        __shared__ float rA[128], rB[128];
        rA[tid] = rsqrtf(g_nAL[0][pair][tid] + g_nAL[1][pair][tid]);
        rB[tid] = rsqrtf(g_nBL[0][pair][tid] + g_nBL[1][pair][tid]);
        __syncthreads();
        const float* d0 = g_dotL0 + (size_t)pair * 16384;
        const float* d1 = g_dotL1 + (size_t)pair * 16384;
        for (int idx = tid * 4; idx < 16384; idx += 512) {
            float4 a4 = *(const float4*)(d0 + idx);
            float4 b4 = *(const float4*)(d1 + idx);
            int row = idx >> 7, col = idx & 127;
            float ra = rA[row];
            // float index into packed array: ((row>>1)*128 + col)*2 + (row&1)
            int base = ((row >> 1) * 128 + col) * 2 + (row & 1);
            dsm[base + 0] = fmaxf(0.0f, (a4.x + b4.x) * ra * rB[col + 0] - 0.8f) * 5.0f;
            dsm[base + 2] = fmaxf(0.0f, (a4.y + b4.y) * ra * rB[col + 1] - 0.8f) * 5.0f;
            dsm[base + 4] = fmaxf(0.0f, (a4.z + b4.z) * ra * rB[col + 2] - 0.8f) * 5.0f;
            dsm[base + 6] = fmaxf(0.0f, (a4.w + b4.w) * ra * rB[col + 3] - 0.8f) * 5.0f;
        }
    }
    // zero boundary row (192 floats)
    if (tid < 96) {
        bnd[2][tid] = 0.0f;
        bnd[2][tid + 96] = 0.0f;
    }
    __syncthreads();

    int w = tid >> 5, lane = tid & 31;
    int p = (w & 1) * 32 + lane;        // row-pair for DP warps 0,1
    bool dpw = (w < 2);
    const float* bndp = bnd[(w == 0) ? 2 : 0];
    float v0 = 0.0f, v1 = 0.0f, d = 0.0f;

    if (isFsd) {
        const float4* mrow = ((const float4*)dsm) + p * 128;
        for (int tau = 0; tau < NSUP2; ++tau) {
            if (dpw && tau >= w && tau < w + NE) {
                int s0 = (tau - w) * DPK2;
                float4 mgb[DPK2];
                float  bvb[DPK2];
#pragma unroll
                for (int k = 0; k < DPK2; ++k) {
                    int s = s0 + k;
                    int j = s - p;
                    j = (j < 0) ? 0 : ((j > 127) ? 127 : j);
                    mgb[k] = mrow[j];
                    int sm1 = (s > 0) ? s - 1 : 0;
                    bvb[k] = bndp[sm1];
                }
#pragma unroll
                for (int k = 0; k < DPK2; ++k) {
                    int s = s0 + k;
                    float au = __shfl_up_sync(0xffffffffu, v1, 1);
                    float a = (lane == 0) ? bvb[k] : au;
                    // top cell: diag=d, up=a, left=v0
                    float x1 = mgb[k].y + a, x2 = mgb[k].y + v0;
                    float mx = fmaxf(fmaxf(d, x1), x2);
                    float e = ex2f(d - mx) + ex2f(x1 - mx) + ex2f(x2 - mx);
                    float nv0 = mgb[k].x + mx + lg2f(e);
                    // bottom cell: diag=v0(old), up=nv0, left=v1
                    float y1 = mgb[k].w + nv0, y2 = mgb[k].w + v1;
                    float my = fmaxf(fmaxf(v0, y1), y2);
                    float e2 = ex2f(v0 - my) + ex2f(y1 - my) + ex2f(y2 - my);
                    float nv1 = mgb[k].z + my + lg2f(e2);
                    bool actv = ((unsigned)(s - p) < 128u);
                    v0 = actv ? nv0 : v0;
                    v1 = actv ? nv1 : v1;
                    d = a;
                    if (lane == 31) bnd[w][s] = v1;
                }
            }
            __syncthreads();
        }
        if (tid == 63) g_dpres[b] = v1 * FSD_UNSCALE;
    } else {
        const float2* srow = ((const float2*)dsm) + p * 128;
        for (int tau = 0; tau < NSUP2; ++tau) {
            if (dpw && tau >= w && tau < w + NE) {
                int s0 = (tau - w) * DPK2;
                float2 svb[DPK2];
                float  bvb[DPK2];
#pragma unroll
                for (int k = 0; k < DPK2; ++k) {
                    int s = s0 + k;
                    int j = s - p;
                    j = (j < 0) ? 0 : ((j > 127) ? 127 : j);
                    svb[k] = srow[j];
                    int sm1 = (s > 0) ? s - 1 : 0;
                    bvb[k] = bndp[sm1];
                }
#pragma unroll
                for (int k = 0; k < DPK2; ++k) {
                    int s = s0 + k;
                    float au = __shfl_up_sync(0xffffffffu, v1, 1);
                    float a = (lane == 0) ? bvb[k] : au;
                    float nv0 = (svb[k].x > 0.5f) ? d + svb[k].x : fmaxf(a, v0);
                    float nv1 = (svb[k].y > 0.5f) ? v0 + svb[k].y : fmaxf(nv0, v1);
                    bool actv = ((unsigned)(s - p) < 128u);
                    v0 = actv ? nv0 : v0;
                    v1 = actv ? nv1 : v1;
                    d = a;
                    if (lane == 31) bnd[w][s] = v1;
                }
            }
            __syncthreads();
        }
        if (tid == 63) g_dpres[b] = v1;
    }

    // completion + final combine by the last finishing block
    if (tid == 63) {
        __threadfence();
        unsigned vdone = atomicAdd(&g_done, 1u);
        if (vdone == 63u) {
            float cls = 0.f, guide = 0.f, feat = 0.f, sparse = 0.f;
#pragma unroll 4
            for (int i = 0; i < 32; ++i) {
                cls    += g_small[i][0];
                guide  += g_small[i][1];
                feat   += g_small[i][2];
                sparse += g_small[i][3];
            }
            volatile float* dp = g_dpres;
            float aa = 0.f, ab = 0.f, pl = 0.f, nl = 0.f;
#pragma unroll 4
            for (int i = 0; i < 16; ++i) {
                aa += dp[i];
                ab += dp[16 + i];
                pl += dp[32 + i];
                nl += dp[48 + i];
            }
            float acm = cls / 32.0f + guide / 32.0f
                      + 5e-5f * (feat / 32.0f) + 2e-4f * (sparse / 64.0f);
            outp[0] = acm + 0.1f * ((nl - pl) / 16.0f)
                          + 0.1f * ((ab - aa) / 16.0f);
            g_done = 0;
        }
    }
}

// ---------------------------------------------------------------------------
// Launch
// ---------------------------------------------------------------------------
extern "C" void kernel_launch(void* const* d_in, const int* in_sizes, int n_in,
                              void* d_out, int out_size) {
    const float* xi  = (const float*)d_in[0];
    const float* xc  = (const float*)d_in[1];
    const float* xb  = (const float*)d_in[2];
    const float* vid = (const float*)d_in[3];
    const float* att = (const float*)d_in[4];
    const float* fi  = (const float*)d_in[5];
    const float* fc  = (const float*)d_in[6];
    const float* fb  = (const float*)d_in[7];
    const float* cas = (const float*)d_in[8];
    const float* lcs = (const float*)d_in[9];
    const float* act = (const float*)d_in[10];
    const float* bak = (const float*)d_in[11];
    const int*   pos = (const int*)d_in[12];
    const int*   neg = (const int*)d_in[13];
    float* out = (float*)d_out;

    const int dp_smem = 2 * 16384 * (int)sizeof(float);   // 128 KB
    cudaFuncSetAttribute(k_dp, cudaFuncAttributeMaxDynamicSharedMemorySize, dp_smem);

    k_gemm<<<288, 256>>>(lcs, act, bak, pos, neg,
                         xi, xc, xb, vid, att, fi, fc, fb, cas);
    k_dp<<<64, 128, dp_smem>>>(out);
}